// round 1
// baseline (speedup 1.0000x reference)
#include <cuda_runtime.h>
#include <cstdint>

// ---------------------------------------------------------------------------
// 2-layer GAT:
//   L1: IN=128 -> HEADS=4 x HID=16 (concat -> 64), self-loops, softmax over dst
//   L2: 64 -> OUT=8, heads=1, mean(=identity)
// Outputs (tuple order): out2 [N,8] then x_emb [N,64]
// ---------------------------------------------------------------------------

#define NODES 100000
#define EDGES 1600000
#define EPMAX (NODES + EDGES)

// scratch (static device globals; no allocation allowed)
__device__ float    g_xl1[(size_t)NODES * 64];
__device__ float    g_as1[NODES * 4];
__device__ float    g_ad1[NODES * 4];
__device__ unsigned g_m1[NODES * 4];
__device__ float    g_s1[NODES * 4];
__device__ float    g_e1[(size_t)EPMAX * 4];
__device__ float    g_xl2[NODES * 8];
__device__ float    g_as2[NODES];
__device__ float    g_ad2[NODES];
__device__ unsigned g_m2[NODES];
__device__ float    g_s2[NODES];
__device__ float    g_e2[EPMAX];
__device__ int      g_is64;   // 1 if edge_index is int64, 0 if int32

// order-preserving float <-> u32 map for atomicMax
__device__ __forceinline__ unsigned fenc(float f) {
    unsigned b = __float_as_uint(f);
    return (b & 0x80000000u) ? ~b : (b | 0x80000000u);
}
__device__ __forceinline__ float fdec(unsigned u) {
    return __uint_as_float((u & 0x80000000u) ? (u ^ 0x80000000u) : ~u);
}
__device__ __forceinline__ float lrelu(float x) {
    return x > 0.0f ? x : 0.2f * x;
}

// edge i -> (src, dst); i >= E are self loops. Handles int32/int64 edge_index.
__device__ __forceinline__ void edge_sd(const int* __restrict__ ei, int i, int E,
                                        int is64, int& s, int& d) {
    if (i < E) {
        if (is64) { s = ei[2 * i]; d = ei[2 * (E + i)]; }
        else      { s = ei[i];     d = ei[E + i]; }
    } else {
        s = d = i - E;
    }
}

// ---------------------------------------------------------------------------
__global__ void init_kernel(float* __restrict__ out, int total_out) {
    int i = blockIdx.x * 256 + threadIdx.x;
    if (i < total_out) out[i] = 0.0f;
    if (i < NODES * 4) { g_m1[i] = 0u; g_s1[i] = 0.0f; }
    if (i < NODES)     { g_m2[i] = 0u; g_s2[i] = 0.0f; }
}

// Detect edge dtype width: int64 little-endian with values < 2^31 has every odd
// 32-bit word zero. A real int32 edge list (random node ids) cannot.
__global__ void detect_kernel(const int* __restrict__ ei32, int nwords) {
    __shared__ int any;
    if (threadIdx.x == 0) any = 0;
    __syncthreads();
    for (int i = threadIdx.x * 2 + 1; i < nwords; i += 2 * blockDim.x) {
        if (ei32[i] != 0) { any = 1; break; }
    }
    __syncthreads();
    if (threadIdx.x == 0) g_is64 = any ? 0 : 1;
}

// ---------------------------------------------------------------------------
// GEMM1: xl1 = x @ W1  ([N,128]@[128,64]), plus alpha_s/alpha_d per (node,head).
// 256 threads, 64 nodes/block, each thread: 4 cols x 4 nodes.
// dynamic smem: sW[128*64] | sX[64*132] | sAS[256] | sAD[256]
// ---------------------------------------------------------------------------
#define GEMM1_SMEM ((128*64 + 64*132 + 256 + 256) * 4)

__global__ void gemm1_kernel(const float* __restrict__ x, const float* __restrict__ W1,
                             const float* __restrict__ asw, const float* __restrict__ adw,
                             int N) {
    extern __shared__ float smem[];
    float* sW  = smem;                // 8192
    float* sX  = sW + 128 * 64;       // 64*132
    float* sAS = sX + 64 * 132;       // 256
    float* sAD = sAS + 256;           // 256

    int t = threadIdx.x;
    int nb = blockIdx.x * 64;

    // load W1 (8192 floats) as float4
    const float4* W4 = (const float4*)W1;
    float4* sW4 = (float4*)sW;
    for (int i = t; i < 2048; i += 256) sW4[i] = W4[i];
    // load x rows (64 x 128), padded row stride 132 to dodge bank conflicts
    for (int i = t; i < 2048; i += 256) {
        int r = i >> 5, j = i & 31;
        float4 v = make_float4(0.f, 0.f, 0.f, 0.f);
        if (nb + r < N) v = ((const float4*)x)[(size_t)(nb + r) * 32 + j];
        *(float4*)(&sX[r * 132 + j * 4]) = v;
    }
    sAS[t] = 0.0f; sAD[t] = 0.0f;
    __syncthreads();

    int tx = t & 15, ty = t >> 4;
    int c0 = tx * 4, n0 = ty * 4;
    float acc[4][4] = {};
#pragma unroll 4
    for (int k = 0; k < 128; k++) {
        float4 w = *(const float4*)(&sW[k * 64 + c0]);
#pragma unroll
        for (int i = 0; i < 4; i++) {
            float xv = sX[(n0 + i) * 132 + k];
            acc[i][0] = fmaf(xv, w.x, acc[i][0]);
            acc[i][1] = fmaf(xv, w.y, acc[i][1]);
            acc[i][2] = fmaf(xv, w.z, acc[i][2]);
            acc[i][3] = fmaf(xv, w.w, acc[i][3]);
        }
    }

    // head for columns c0..c0+3 (they never cross a 16-col head boundary)
    int h = tx >> 2;
    float4 aw = *(const float4*)(asw + c0);   // att_src1 flattened [4*16]
    float4 dw = *(const float4*)(adw + c0);
#pragma unroll
    for (int i = 0; i < 4; i++) {
        int node = nb + n0 + i;
        if (node < N) {
            float4 v = make_float4(acc[i][0], acc[i][1], acc[i][2], acc[i][3]);
            *(float4*)(&g_xl1[(size_t)node * 64 + c0]) = v;
            float ps = v.x * aw.x + v.y * aw.y + v.z * aw.z + v.w * aw.w;
            float pd = v.x * dw.x + v.y * dw.y + v.z * dw.z + v.w * dw.w;
            atomicAdd(&sAS[(n0 + i) * 4 + h], ps);
            atomicAdd(&sAD[(n0 + i) * 4 + h], pd);
        }
    }
    __syncthreads();
    int node = nb + (t >> 2);
    if (node < N) {
        g_as1[node * 4 + (t & 3)] = sAS[t];
        g_ad1[node * 4 + (t & 3)] = sAD[t];
    }
}

// ---------------------------------------------------------------------------
// Layer-1 edge passes
// ---------------------------------------------------------------------------
__global__ void passA1(const int* __restrict__ ei, int E, int EP) {
    int i = blockIdx.x * 256 + threadIdx.x;
    if (i >= EP) return;
    int s, d; edge_sd(ei, i, E, g_is64, s, d);
    float4 a = *(const float4*)&g_as1[s * 4];
    float4 b = *(const float4*)&g_ad1[d * 4];
    float4 e;
    e.x = lrelu(a.x + b.x);
    e.y = lrelu(a.y + b.y);
    e.z = lrelu(a.z + b.z);
    e.w = lrelu(a.w + b.w);
    *(float4*)&g_e1[(size_t)i * 4] = e;
    atomicMax(&g_m1[d * 4 + 0], fenc(e.x));
    atomicMax(&g_m1[d * 4 + 1], fenc(e.y));
    atomicMax(&g_m1[d * 4 + 2], fenc(e.z));
    atomicMax(&g_m1[d * 4 + 3], fenc(e.w));
}

__global__ void passB1(const int* __restrict__ ei, int E, int EP) {
    int i = blockIdx.x * 256 + threadIdx.x;
    if (i >= EP) return;
    int s, d; edge_sd(ei, i, E, g_is64, s, d);
    float4 e = *(float4*)&g_e1[(size_t)i * 4];
    uint4  m = *(uint4*)&g_m1[d * 4];
    e.x = __expf(e.x - fdec(m.x));
    e.y = __expf(e.y - fdec(m.y));
    e.z = __expf(e.z - fdec(m.z));
    e.w = __expf(e.w - fdec(m.w));
    *(float4*)&g_e1[(size_t)i * 4] = e;
    atomicAdd(&g_s1[d * 4 + 0], e.x);
    atomicAdd(&g_s1[d * 4 + 1], e.y);
    atomicAdd(&g_s1[d * 4 + 2], e.z);
    atomicAdd(&g_s1[d * 4 + 3], e.w);
}

// scatter: xemb[d, h, c] += xl1[s, h, c] * alpha[e, h]; 64 threads per edge
__global__ void passC1(const int* __restrict__ ei, int E, int EP,
                       float* __restrict__ xemb) {
    __shared__ float sAl[4][4];
    int t = threadIdx.x;
    int le = t >> 6, lane = t & 63;
    int e = blockIdx.x * 4 + le;
    int s = 0, d = 0;
    if (e < EP) edge_sd(ei, e, E, g_is64, s, d);
    if (e < EP && lane < 4)
        sAl[le][lane] = g_e1[(size_t)e * 4 + lane] / (g_s1[d * 4 + lane] + 1e-16f);
    __syncthreads();
    if (e < EP) {
        int h = lane >> 4;
        atomicAdd(&xemb[(size_t)d * 64 + lane],
                  g_xl1[(size_t)s * 64 + lane] * sAl[le][h]);
    }
}

// ---------------------------------------------------------------------------
// Layer-2 prep: x_emb += b1 (write back), h=relu(x_emb), xl2 = h @ W2,
// alpha_s2/alpha_d2. One warp per node.
// ---------------------------------------------------------------------------
__global__ void layer2_prep(float* __restrict__ xemb, const float* __restrict__ b1,
                            const float* __restrict__ W2,
                            const float* __restrict__ as2w, const float* __restrict__ ad2w,
                            int N) {
    __shared__ float sW2[64 * 8];
    int t = threadIdx.x;
    for (int i = t; i < 512; i += 256) sW2[i] = W2[i];
    __syncthreads();
    int warp = t >> 5, lane = t & 31;
    int node = blockIdx.x * 8 + warp;
    if (node >= N) return;

    float v0 = xemb[(size_t)node * 64 + lane]      + b1[lane];
    float v1 = xemb[(size_t)node * 64 + 32 + lane] + b1[lane + 32];
    xemb[(size_t)node * 64 + lane]      = v0;
    xemb[(size_t)node * 64 + 32 + lane] = v1;
    float h0 = fmaxf(v0, 0.0f), h1 = fmaxf(v1, 0.0f);

    float p[8];
#pragma unroll
    for (int j = 0; j < 8; j++)
        p[j] = h0 * sW2[lane * 8 + j] + h1 * sW2[(lane + 32) * 8 + j];
#pragma unroll
    for (int off = 16; off; off >>= 1) {
#pragma unroll
        for (int j = 0; j < 8; j++)
            p[j] += __shfl_xor_sync(0xffffffffu, p[j], off);
    }
    if (lane == 0) {
        float ss = 0.0f, dd = 0.0f;
#pragma unroll
        for (int j = 0; j < 8; j++) {
            g_xl2[node * 8 + j] = p[j];
            ss = fmaf(p[j], as2w[j], ss);
            dd = fmaf(p[j], ad2w[j], dd);
        }
        g_as2[node] = ss;
        g_ad2[node] = dd;
    }
}

// ---------------------------------------------------------------------------
// Layer-2 edge passes (H=1, C=8)
// ---------------------------------------------------------------------------
__global__ void passA2(const int* __restrict__ ei, int E, int EP) {
    int i = blockIdx.x * 256 + threadIdx.x;
    if (i >= EP) return;
    int s, d; edge_sd(ei, i, E, g_is64, s, d);
    float e = lrelu(g_as2[s] + g_ad2[d]);
    g_e2[i] = e;
    atomicMax(&g_m2[d], fenc(e));
}

__global__ void passB2(const int* __restrict__ ei, int E, int EP) {
    int i = blockIdx.x * 256 + threadIdx.x;
    if (i >= EP) return;
    int s, d; edge_sd(ei, i, E, g_is64, s, d);
    float e = __expf(g_e2[i] - fdec(g_m2[d]));
    g_e2[i] = e;
    atomicAdd(&g_s2[d], e);
}

// 8 threads per edge
__global__ void passC2(const int* __restrict__ ei, int E, int EP,
                       float* __restrict__ out2) {
    int idx = blockIdx.x * 256 + threadIdx.x;
    int e = idx >> 3, c = idx & 7;
    if (e >= EP) return;
    int s, d; edge_sd(ei, e, E, g_is64, s, d);
    float alpha = g_e2[e] / (g_s2[d] + 1e-16f);
    atomicAdd(&out2[(size_t)d * 8 + c], g_xl2[s * 8 + c] * alpha);
}

__global__ void bias2_kernel(float* __restrict__ out2, const float* __restrict__ b2, int n) {
    int i = blockIdx.x * 256 + threadIdx.x;
    if (i < n) out2[i] += b2[i & 7];
}

// ---------------------------------------------------------------------------
extern "C" void kernel_launch(void* const* d_in, const int* in_sizes, int n_in,
                              void* d_out, int out_size) {
    const float* x    = (const float*)d_in[0];
    const int*   ei   = (const int*)d_in[1];   // int32 view; width auto-detected
    const float* W1   = (const float*)d_in[2];
    const float* as1w = (const float*)d_in[3];
    const float* ad1w = (const float*)d_in[4];
    const float* b1   = (const float*)d_in[5];
    const float* W2   = (const float*)d_in[6];
    const float* as2w = (const float*)d_in[7];
    const float* ad2w = (const float*)d_in[8];
    const float* b2   = (const float*)d_in[9];
    float* out = (float*)d_out;

    int N  = in_sizes[0] / 128;   // 100000
    int E  = in_sizes[1] / 2;     // 1600000 (element count same for i32/i64)
    int EP = E + N;

    float* out2 = out;                    // [N, 8]
    float* xemb = out + (size_t)N * 8;    // [N, 64]
    int total_out = N * 72;

    cudaFuncSetAttribute(gemm1_kernel, cudaFuncAttributeMaxDynamicSharedMemorySize,
                         GEMM1_SMEM);

    init_kernel<<<(total_out + 255) / 256, 256>>>(out, total_out);
    {
        int nwords = in_sizes[1];
        if (nwords > 65536) nwords = 65536;
        detect_kernel<<<1, 256>>>(ei, nwords);
    }

    gemm1_kernel<<<(N + 63) / 64, 256, GEMM1_SMEM>>>(x, W1, as1w, ad1w, N);

    int eb = (EP + 255) / 256;
    passA1<<<eb, 256>>>(ei, E, EP);
    passB1<<<eb, 256>>>(ei, E, EP);
    passC1<<<(EP + 3) / 4, 256>>>(ei, E, EP, xemb);

    layer2_prep<<<(N + 7) / 8, 256>>>(xemb, b1, W2, as2w, ad2w, N);

    passA2<<<eb, 256>>>(ei, E, EP);
    passB2<<<eb, 256>>>(ei, E, EP);
    passC2<<<(EP * 8 + 255) / 256, 256>>>(ei, E, EP, out2);

    bias2_kernel<<<(N * 8 + 255) / 256, 256>>>(out2, b2, N * 8);
}

// round 2
// speedup vs baseline: 2.5154x; 2.5154x over previous
#include <cuda_runtime.h>
#include <cstdint>

// ---------------------------------------------------------------------------
// 2-layer GAT, fused softmax-free formulation:
//   out[d] = (sum_e exp(lrelu(as[s]+ad[d])) * xl[s]) / (sum_e exp(...)) + bias
// One edge pass per layer; normalization deferred to per-node kernels.
// Outputs (tuple order): out2 [N,8] then x_emb [N,64]
// ---------------------------------------------------------------------------

#define NODES 100000
#define EDGES 1600000
#define EPMAX (NODES + EDGES)

// scratch (static device globals; no allocation allowed)
__device__ float    g_xl1[(size_t)NODES * 64];
__device__ float    g_as1[NODES * 4];
__device__ float    g_ad1[NODES * 4];
__device__ float    g_s1[NODES * 4];
__device__ float    g_xl2[NODES * 8];
__device__ float    g_as2[NODES];
__device__ float    g_ad2[NODES];
__device__ float    g_s2[NODES];
__device__ int      g_is64;   // 1 if edge_index is int64, 0 if int32

__device__ __forceinline__ float lrelu(float x) {
    return x > 0.0f ? x : 0.2f * x;
}

// vectorized fire-and-forget reduction (sm_90+)
__device__ __forceinline__ void red_add_v4(float* p, float a, float b, float c, float d) {
    asm volatile("red.global.add.v4.f32 [%0], {%1,%2,%3,%4};"
                 :: "l"(p), "f"(a), "f"(b), "f"(c), "f"(d) : "memory");
}

// edge i -> (src, dst); i >= E are self loops. Handles int32/int64 edge_index.
__device__ __forceinline__ void edge_sd(const int* __restrict__ ei, int i, int E,
                                        int is64, int& s, int& d) {
    if (i < E) {
        if (is64) { s = ei[2 * i]; d = ei[2 * (E + i)]; }
        else      { s = ei[i];     d = ei[E + i]; }
    } else {
        s = d = i - E;
    }
}

// ---------------------------------------------------------------------------
__global__ void init_kernel(float* __restrict__ out, int total_out) {
    int i = blockIdx.x * 256 + threadIdx.x;
    if (i < total_out) out[i] = 0.0f;
    if (i < NODES * 4) g_s1[i] = 0.0f;
    if (i < NODES)     g_s2[i] = 0.0f;
}

// Detect edge dtype width: int64 little-endian with values < 2^31 has every odd
// 32-bit word zero. A real int32 edge list (random node ids) cannot.
__global__ void detect_kernel(const int* __restrict__ ei32, int nwords) {
    __shared__ int any;
    if (threadIdx.x == 0) any = 0;
    __syncthreads();
    for (int i = threadIdx.x * 2 + 1; i < nwords; i += 2 * blockDim.x) {
        if (ei32[i] != 0) { any = 1; break; }
    }
    __syncthreads();
    if (threadIdx.x == 0) g_is64 = any ? 0 : 1;
}

// ---------------------------------------------------------------------------
// GEMM1: xl1 = x @ W1  ([N,128]@[128,64]), plus alpha_s/alpha_d per (node,head).
// 256 threads, 64 nodes/block, each thread: 4 cols x 4 nodes.
// ---------------------------------------------------------------------------
#define GEMM1_SMEM ((128*64 + 64*132 + 256 + 256) * 4)

__global__ void gemm1_kernel(const float* __restrict__ x, const float* __restrict__ W1,
                             const float* __restrict__ asw, const float* __restrict__ adw,
                             int N) {
    extern __shared__ float smem[];
    float* sW  = smem;                // 8192
    float* sX  = sW + 128 * 64;       // 64*132
    float* sAS = sX + 64 * 132;       // 256
    float* sAD = sAS + 256;           // 256

    int t = threadIdx.x;
    int nb = blockIdx.x * 64;

    const float4* W4 = (const float4*)W1;
    float4* sW4 = (float4*)sW;
    for (int i = t; i < 2048; i += 256) sW4[i] = W4[i];
    for (int i = t; i < 2048; i += 256) {
        int r = i >> 5, j = i & 31;
        float4 v = make_float4(0.f, 0.f, 0.f, 0.f);
        if (nb + r < N) v = ((const float4*)x)[(size_t)(nb + r) * 32 + j];
        *(float4*)(&sX[r * 132 + j * 4]) = v;
    }
    sAS[t] = 0.0f; sAD[t] = 0.0f;
    __syncthreads();

    int tx = t & 15, ty = t >> 4;
    int c0 = tx * 4, n0 = ty * 4;
    float acc[4][4] = {};
#pragma unroll 4
    for (int k = 0; k < 128; k++) {
        float4 w = *(const float4*)(&sW[k * 64 + c0]);
#pragma unroll
        for (int i = 0; i < 4; i++) {
            float xv = sX[(n0 + i) * 132 + k];
            acc[i][0] = fmaf(xv, w.x, acc[i][0]);
            acc[i][1] = fmaf(xv, w.y, acc[i][1]);
            acc[i][2] = fmaf(xv, w.z, acc[i][2]);
            acc[i][3] = fmaf(xv, w.w, acc[i][3]);
        }
    }

    int h = tx >> 2;   // columns c0..c0+3 never cross a 16-col head boundary
    float4 aw = *(const float4*)(asw + c0);
    float4 dw = *(const float4*)(adw + c0);
#pragma unroll
    for (int i = 0; i < 4; i++) {
        int node = nb + n0 + i;
        if (node < N) {
            float4 v = make_float4(acc[i][0], acc[i][1], acc[i][2], acc[i][3]);
            *(float4*)(&g_xl1[(size_t)node * 64 + c0]) = v;
            float ps = v.x * aw.x + v.y * aw.y + v.z * aw.z + v.w * aw.w;
            float pd = v.x * dw.x + v.y * dw.y + v.z * dw.z + v.w * dw.w;
            atomicAdd(&sAS[(n0 + i) * 4 + h], ps);
            atomicAdd(&sAD[(n0 + i) * 4 + h], pd);
        }
    }
    __syncthreads();
    int node = nb + (t >> 2);
    if (node < N) {
        g_as1[node * 4 + (t & 3)] = sAS[t];
        g_ad1[node * 4 + (t & 3)] = sAD[t];
    }
}

// ---------------------------------------------------------------------------
// Layer-1 fused edge pass: 16 threads per edge, thread q owns channels [4q,4q+4)
// (head h = q>>2). Unnormalized scatter + per-dst exp-sum.
// ---------------------------------------------------------------------------
__global__ void edge1_kernel(const int* __restrict__ ei, int E, int EP,
                             float* __restrict__ xemb) {
    int idx = blockIdx.x * 256 + threadIdx.x;
    int e = idx >> 4, q = idx & 15;
    if (e >= EP) return;
    int s, d; edge_sd(ei, e, E, g_is64, s, d);
    int h = q >> 2;
    float ev = __expf(lrelu(g_as1[s * 4 + h] + g_ad1[d * 4 + h]));
    if ((q & 3) == 0) atomicAdd(&g_s1[d * 4 + h], ev);   // q=0,4,8,12 -> h=0..3
    float4 xv = *(const float4*)&g_xl1[(size_t)s * 64 + q * 4];
    red_add_v4(&xemb[(size_t)d * 64 + q * 4],
               ev * xv.x, ev * xv.y, ev * xv.z, ev * xv.w);
}

// ---------------------------------------------------------------------------
// Layer-2 prep: normalize x_emb (div by s1) + b1, write back; h=relu;
// xl2 = h @ W2; alpha_s2/alpha_d2. One warp per node.
// ---------------------------------------------------------------------------
__global__ void layer2_prep(float* __restrict__ xemb, const float* __restrict__ b1,
                            const float* __restrict__ W2,
                            const float* __restrict__ as2w, const float* __restrict__ ad2w,
                            int N) {
    __shared__ float sW2[64 * 8];
    int t = threadIdx.x;
    for (int i = t; i < 512; i += 256) sW2[i] = W2[i];
    __syncthreads();
    int warp = t >> 5, lane = t & 31;
    int node = blockIdx.x * 8 + warp;
    if (node >= N) return;

    float inv0 = 1.0f / (g_s1[node * 4 + (lane >> 4)] + 1e-16f);
    float inv1 = 1.0f / (g_s1[node * 4 + ((lane + 32) >> 4)] + 1e-16f);
    float v0 = xemb[(size_t)node * 64 + lane]      * inv0 + b1[lane];
    float v1 = xemb[(size_t)node * 64 + 32 + lane] * inv1 + b1[lane + 32];
    xemb[(size_t)node * 64 + lane]      = v0;
    xemb[(size_t)node * 64 + 32 + lane] = v1;
    float h0 = fmaxf(v0, 0.0f), h1 = fmaxf(v1, 0.0f);

    float p[8];
#pragma unroll
    for (int j = 0; j < 8; j++)
        p[j] = h0 * sW2[lane * 8 + j] + h1 * sW2[(lane + 32) * 8 + j];
#pragma unroll
    for (int off = 16; off; off >>= 1) {
#pragma unroll
        for (int j = 0; j < 8; j++)
            p[j] += __shfl_xor_sync(0xffffffffu, p[j], off);
    }
    if (lane == 0) {
        float ss = 0.0f, dd = 0.0f;
#pragma unroll
        for (int j = 0; j < 8; j++) {
            g_xl2[node * 8 + j] = p[j];
            ss = fmaf(p[j], as2w[j], ss);
            dd = fmaf(p[j], ad2w[j], dd);
        }
        g_as2[node] = ss;
        g_ad2[node] = dd;
    }
}

// ---------------------------------------------------------------------------
// Layer-2 fused edge pass: one thread per edge (C=8, H=1).
// ---------------------------------------------------------------------------
__global__ void edge2_kernel(const int* __restrict__ ei, int E, int EP,
                             float* __restrict__ out2) {
    int e = blockIdx.x * 256 + threadIdx.x;
    if (e >= EP) return;
    int s, d; edge_sd(ei, e, E, g_is64, s, d);
    float ev = __expf(lrelu(g_as2[s] + g_ad2[d]));
    atomicAdd(&g_s2[d], ev);
    float4 a = *(const float4*)&g_xl2[s * 8];
    float4 b = *(const float4*)&g_xl2[s * 8 + 4];
    red_add_v4(&out2[(size_t)d * 8],     ev * a.x, ev * a.y, ev * a.z, ev * a.w);
    red_add_v4(&out2[(size_t)d * 8 + 4], ev * b.x, ev * b.y, ev * b.z, ev * b.w);
}

__global__ void finalize2_kernel(float* __restrict__ out2, const float* __restrict__ b2,
                                 int n) {
    int i = blockIdx.x * 256 + threadIdx.x;
    if (i < n) out2[i] = out2[i] / (g_s2[i >> 3] + 1e-16f) + b2[i & 7];
}

// ---------------------------------------------------------------------------
extern "C" void kernel_launch(void* const* d_in, const int* in_sizes, int n_in,
                              void* d_out, int out_size) {
    const float* x    = (const float*)d_in[0];
    const int*   ei   = (const int*)d_in[1];
    const float* W1   = (const float*)d_in[2];
    const float* as1w = (const float*)d_in[3];
    const float* ad1w = (const float*)d_in[4];
    const float* b1   = (const float*)d_in[5];
    const float* W2   = (const float*)d_in[6];
    const float* as2w = (const float*)d_in[7];
    const float* ad2w = (const float*)d_in[8];
    const float* b2   = (const float*)d_in[9];
    float* out = (float*)d_out;

    int N  = in_sizes[0] / 128;
    int E  = in_sizes[1] / 2;
    int EP = E + N;

    float* out2 = out;                    // [N, 8]
    float* xemb = out + (size_t)N * 8;    // [N, 64]
    int total_out = N * 72;

    cudaFuncSetAttribute(gemm1_kernel, cudaFuncAttributeMaxDynamicSharedMemorySize,
                         GEMM1_SMEM);

    init_kernel<<<(total_out + 255) / 256, 256>>>(out, total_out);
    {
        int nwords = in_sizes[1];
        if (nwords > 65536) nwords = 65536;
        detect_kernel<<<1, 256>>>(ei, nwords);
    }

    gemm1_kernel<<<(N + 63) / 64, 256, GEMM1_SMEM>>>(x, W1, as1w, ad1w, N);

    edge1_kernel<<<(EP * 16 + 255) / 256, 256>>>(ei, E, EP, xemb);

    layer2_prep<<<(N + 7) / 8, 256>>>(xemb, b1, W2, as2w, ad2w, N);

    edge2_kernel<<<(EP + 255) / 256, 256>>>(ei, E, EP, out2);

    finalize2_kernel<<<(N * 8 + 255) / 256, 256>>>(out2, b2, N * 8);
}